// round 1
// baseline (speedup 1.0000x reference)
#include <cuda_runtime.h>
#include <math.h>
#include <stdint.h>

#define DIM 256
#define BM 128
#define KC 32
#define ASTRIDE 260   // A smem row stride (floats): bank = (4g+t) unique -> conflict-free
#define WSTRIDE 264   // W smem row stride (floats): bank = (8k+g) unique -> conflict-free
#define MAX_CFG 100000

// scratch for factored precompute (static __device__ globals: allocation-free)
__device__ float g_U [(size_t)MAX_CFG * DIM];
__device__ float g_G2[(size_t)MAX_CFG * DIM];

// smem layout: [A: BM*ASTRIDE f32][W: KC*WSTRIDE u32][misc: 2KB]
#define SMEM_A_BYTES (BM * ASTRIDE * 4)
#define SMEM_W_BYTES (KC * WSTRIDE * 4)
#define SMEM_TOTAL   (SMEM_A_BYTES + SMEM_W_BYTES + 2048)

__device__ __forceinline__ unsigned f2tf(float x) {
    unsigned r; asm("cvt.rna.tf32.f32 %0, %1;" : "=r"(r) : "f"(x)); return r;
}

__device__ __forceinline__ void mma_tf32(float c[4], const unsigned a[4], const unsigned b[2]) {
    asm volatile(
        "mma.sync.aligned.m16n8k8.row.col.f32.tf32.tf32.f32 "
        "{%0,%1,%2,%3}, {%4,%5,%6,%7}, {%8,%9}, {%0,%1,%2,%3};"
        : "+f"(c[0]), "+f"(c[1]), "+f"(c[2]), "+f"(c[3])
        : "r"(a[0]), "r"(a[1]), "r"(a[2]), "r"(a[3]), "r"(b[0]), "r"(b[1]));
}

// One 128x256x256 GEMM tile: sA (fp32, gathered rows) @ Wglob (streamed via sW
// in tf32). acc is zeroed here. Warp layout: warp_m in [0,4), warp_n in [0,2),
// warp tile 32x128, m16n8k8 frags.
__device__ __forceinline__ void gemm_256(
    const float* __restrict__ sA, unsigned* __restrict__ sW,
    const float* __restrict__ Wglob, float acc[2][16][4],
    int tid, int warp_m, int warp_n, int g, int t)
{
#pragma unroll
    for (int mf = 0; mf < 2; mf++)
#pragma unroll
        for (int nf = 0; nf < 16; nf++)
#pragma unroll
            for (int i = 0; i < 4; i++) acc[mf][nf][i] = 0.f;

    for (int kc = 0; kc < DIM; kc += KC) {
        __syncthreads();  // protect sW reuse + order prior sA writers
        // load W chunk [KC x 256], convert to tf32 at fill
        for (int i = tid; i < KC * (DIM / 4); i += 256) {
            int k  = i >> 6;
            int c4 = (i & 63) * 4;
            float4 v = *(const float4*)(Wglob + (size_t)(kc + k) * DIM + c4);
            uint4 w;
            w.x = f2tf(v.x); w.y = f2tf(v.y); w.z = f2tf(v.z); w.w = f2tf(v.w);
            *(uint4*)(sW + k * WSTRIDE + c4) = w;
        }
        __syncthreads();

#pragma unroll
        for (int ks = 0; ks < KC; ks += 8) {
            unsigned a[2][4];
#pragma unroll
            for (int mf = 0; mf < 2; mf++) {
                const float* p = sA + (warp_m * 32 + mf * 16 + g) * ASTRIDE + (kc + ks) + t;
                a[mf][0] = f2tf(p[0]);
                a[mf][1] = f2tf(p[8 * ASTRIDE]);
                a[mf][2] = f2tf(p[4]);
                a[mf][3] = f2tf(p[8 * ASTRIDE + 4]);
            }
            unsigned b[16][2];
#pragma unroll
            for (int nf = 0; nf < 16; nf++) {
                const unsigned* p = sW + (ks + t) * WSTRIDE + warp_n * 128 + nf * 8 + g;
                b[nf][0] = p[0];
                b[nf][1] = p[4 * WSTRIDE];
            }
#pragma unroll
            for (int mf = 0; mf < 2; mf++)
#pragma unroll
                for (int nf = 0; nf < 16; nf++)
                    mma_tf32(acc[mf][nf], a[mf], b[nf]);
        }
    }
}

// Kernel A: U = tanh(cfg @ Wu + bu); G2 = U @ Wg2 + bg  (per 128-row tile, fused)
__global__ void __launch_bounds__(256, 1)
kA(const float* __restrict__ cfg, const float* __restrict__ Wu,
   const float* __restrict__ bu, const float* __restrict__ Wg2,
   const float* __restrict__ bg, int n_cfg)
{
    extern __shared__ char smem[];
    float*    sA  = (float*)smem;
    unsigned* sW  = (unsigned*)(smem + SMEM_A_BYTES);
    float*    sBu = (float*)(smem + SMEM_A_BYTES + SMEM_W_BYTES);
    float*    sBg = sBu + DIM;

    int tid = threadIdx.x;
    int warp = tid >> 5, lane = tid & 31;
    int warp_m = warp >> 1, warp_n = warp & 1;
    int g = lane >> 2, t = lane & 3;
    int r0 = blockIdx.x * BM;

    if (tid < DIM) { sBu[tid] = bu[tid]; sBg[tid] = bg[tid]; }

    // load cfg tile (zero-pad tail rows)
    for (int i = tid; i < BM * (DIM / 4); i += 256) {
        int row = i >> 6;
        int c4  = (i & 63) * 4;
        float4 v = make_float4(0.f, 0.f, 0.f, 0.f);
        if (r0 + row < n_cfg)
            v = *(const float4*)(cfg + (size_t)(r0 + row) * DIM + c4);
        *(float4*)(sA + row * ASTRIDE + c4) = v;
    }

    float acc[2][16][4];
    gemm_256(sA, sW, Wu, acc, tid, warp_m, warp_n, g, t);
    __syncthreads();  // all GEMM1 reads of sA complete before u overwrites it

    // epilogue 1: u = tanh(. + bu) -> sA (for GEMM2) and g_U
#pragma unroll
    for (int mf = 0; mf < 2; mf++)
#pragma unroll
        for (int nf = 0; nf < 16; nf++)
#pragma unroll
            for (int i = 0; i < 4; i++) {
                int row_l = warp_m * 32 + mf * 16 + g + ((i >= 2) ? 8 : 0);
                int col   = warp_n * 128 + nf * 8 + 2 * t + (i & 1);
                float u = tanhf(acc[mf][nf][i] + sBu[col]);
                sA[row_l * ASTRIDE + col] = u;
                if (r0 + row_l < n_cfg)
                    g_U[(size_t)(r0 + row_l) * DIM + col] = u;
            }
    // gemm_256's leading __syncthreads orders the sA writes above

    gemm_256(sA, sW, Wg2, acc, tid, warp_m, warp_n, g, t);

    // epilogue 2: G2 = . + bg
#pragma unroll
    for (int mf = 0; mf < 2; mf++)
#pragma unroll
        for (int nf = 0; nf < 16; nf++)
#pragma unroll
            for (int i = 0; i < 4; i++) {
                int row_l = warp_m * 32 + mf * 16 + g + ((i >= 2) ? 8 : 0);
                int col   = warp_n * 128 + nf * 8 + 2 * t + (i & 1);
                if (r0 + row_l < n_cfg)
                    g_G2[(size_t)(r0 + row_l) * DIM + col] =
                        acc[mf][nf][i] + sBg[col];
            }
}

// Kernel B: for each mapping entry: s = prev[key] @ Wg1 + G2[val];
// z = sigmoid(s); out[key] = z*prev[key] + (1-z)*U[val]
__global__ void __launch_bounds__(256, 1)
kB(const float* __restrict__ prev, const int* __restrict__ keys,
   const int* __restrict__ vals, const float* __restrict__ Wg1,
   float* __restrict__ out, int M)
{
    extern __shared__ char smem[];
    float*    sA   = (float*)smem;
    unsigned* sW   = (unsigned*)(smem + SMEM_A_BYTES);
    int*      sKey = (int*)(smem + SMEM_A_BYTES + SMEM_W_BYTES);
    int*      sVal = sKey + BM;

    int tid = threadIdx.x;
    int warp = tid >> 5, lane = tid & 31;
    int warp_m = warp >> 1, warp_n = warp & 1;
    int g = lane >> 2, t = lane & 3;
    int r0 = blockIdx.x * BM;

    if (tid < BM) {
        int idx = r0 + tid;
        sKey[tid] = (idx < M) ? keys[idx] : 0;
        sVal[tid] = (idx < M) ? vals[idx] : 0;
    }
    __syncthreads();

    // gather prev rows into sA
    for (int i = tid; i < BM * (DIM / 4); i += 256) {
        int row = i >> 6;
        int c4  = (i & 63) * 4;
        float4 v = *(const float4*)(prev + (size_t)sKey[row] * DIM + c4);
        *(float4*)(sA + row * ASTRIDE + c4) = v;
    }

    float acc[2][16][4];
    gemm_256(sA, sW, Wg1, acc, tid, warp_m, warp_n, g, t);

    // epilogue: gate + mix + scatter
#pragma unroll
    for (int mf = 0; mf < 2; mf++)
#pragma unroll
        for (int nf = 0; nf < 16; nf++)
#pragma unroll
            for (int i = 0; i < 4; i++) {
                int row_l = warp_m * 32 + mf * 16 + g + ((i >= 2) ? 8 : 0);
                int col   = warp_n * 128 + nf * 8 + 2 * t + (i & 1);
                if (r0 + row_l < M) {
                    int key = sKey[row_l];
                    int val = sVal[row_l];
                    float pv = sA[row_l * ASTRIDE + col];
                    float s  = acc[mf][nf][i] + g_G2[(size_t)val * DIM + col];
                    float z  = 1.f / (1.f + __expf(-s));
                    float uv = g_U[(size_t)val * DIM + col];
                    out[(size_t)key * DIM + col] = z * pv + (1.f - z) * uv;
                }
            }
}

extern "C" void kernel_launch(void* const* d_in, const int* in_sizes, int n_in,
                              void* d_out, int out_size)
{
    if (n_in < 8) return;
    const float* prev = (const float*)d_in[0];
    const float* cfg  = (const float*)d_in[1];
    const int*   mk   = (const int*)d_in[2];
    const int*   mv   = (const int*)d_in[3];
    const float* Wu   = (const float*)d_in[4];
    const float* bu   = (const float*)d_in[5];
    const float* Wg   = (const float*)d_in[6];
    const float* bg   = (const float*)d_in[7];
    float* out = (float*)d_out;

    int n_cfg = in_sizes[1] / DIM;
    int M     = in_sizes[2];

    cudaFuncSetAttribute(kA, cudaFuncAttributeMaxDynamicSharedMemorySize, SMEM_TOTAL);
    cudaFuncSetAttribute(kB, cudaFuncAttributeMaxDynamicSharedMemorySize, SMEM_TOTAL);

    // base: out <- prev (dense copy; scatter overwrites mapped rows)
    cudaMemcpyAsync(out, prev, (size_t)in_sizes[0] * sizeof(float),
                    cudaMemcpyDeviceToDevice, 0);

    kA<<<(n_cfg + BM - 1) / BM, 256, SMEM_TOTAL>>>(
        cfg, Wu, bu, Wg + DIM * DIM, bg, n_cfg);

    kB<<<(M + BM - 1) / BM, 256, SMEM_TOTAL>>>(
        prev, mk, mv, Wg, out, M);
}

// round 4
// speedup vs baseline: 1.5446x; 1.5446x over previous
#include <cuda_runtime.h>
#include <math.h>
#include <stdint.h>

#define DIM 256
#define BM 64
#define KC 16
#define NC (DIM / KC)     // 16 k-chunks
#define ASTRIDE 260       // sA row stride (floats): lane bank = (4g+t) -> conflict-free
#define WSTRIDE 264       // sW row stride (floats): lane bank = (8t+g) -> conflict-free
#define MAX_CFG 100000
#define NR_AST  500000

// ---- allocation-free scratch (__device__ globals) ----
__device__ float    g_U   [(size_t)MAX_CFG * DIM];
__device__ float    g_G2  [(size_t)MAX_CFG * DIM];
__device__ unsigned g_Wtf [3 * DIM * DIM];   // [0]=Wu, [1]=Wg1, [2]=Wg2 (tf32 bits)
__device__ unsigned char g_flag[NR_AST];

#define SMEM_A_BYTES (BM * ASTRIDE * 4)          // 66560
#define SMEM_W_BYTES (KC * WSTRIDE * 4)          // 16896 (one buffer)
#define SMEM_TOTAL   (SMEM_A_BYTES + 2 * SMEM_W_BYTES + 2048)   // 102400

__device__ __forceinline__ unsigned f2tf(float x) {
    unsigned r; asm("cvt.rna.tf32.f32 %0, %1;" : "=r"(r) : "f"(x)); return r;
}

__device__ __forceinline__ void cp16(void* s, const void* g) {
    unsigned sa = (unsigned)__cvta_generic_to_shared(s);
    asm volatile("cp.async.cg.shared.global [%0], [%1], 16;\n" :: "r"(sa), "l"(g));
}
// zero-fills when src_sz == 0
__device__ __forceinline__ void cp16z(void* s, const void* g, int src_sz) {
    unsigned sa = (unsigned)__cvta_generic_to_shared(s);
    asm volatile("cp.async.cg.shared.global [%0], [%1], 16, %2;\n"
                 :: "r"(sa), "l"(g), "r"(src_sz));
}
#define CP_COMMIT() asm volatile("cp.async.commit_group;\n")

__device__ __forceinline__ void mma_tf32(float c[4], const unsigned a[4], const unsigned b[2]) {
    asm volatile(
        "mma.sync.aligned.m16n8k8.row.col.f32.tf32.tf32.f32 "
        "{%0,%1,%2,%3}, {%4,%5,%6,%7}, {%8,%9}, {%0,%1,%2,%3};"
        : "+f"(c[0]), "+f"(c[1]), "+f"(c[2]), "+f"(c[3])
        : "r"(a[0]), "r"(a[1]), "r"(a[2]), "r"(a[3]), "r"(b[0]), "r"(b[1]));
}

// 64x256x256 tile: sA (fp32) @ Wtf (tf32 global, streamed through a
// double-buffered cp.async pipeline). Caller may have pending (uncommitted)
// cp.asyncs for sA; they are committed with W chunk 0 and complete before use.
// 8 warps: warp_m in [0,2) (32-row band), warp_n in [0,4) (64-col band).
__device__ __forceinline__ void gemm_tile(
    const float* __restrict__ sA, unsigned* __restrict__ sW0, unsigned* __restrict__ sW1,
    const unsigned* __restrict__ Wtf, float acc[2][8][4],
    int tid, int warp_m, int warp_n, int g, int t)
{
#pragma unroll
    for (int mf = 0; mf < 2; mf++)
#pragma unroll
        for (int nf = 0; nf < 8; nf++)
#pragma unroll
            for (int i = 0; i < 4; i++) acc[mf][nf][i] = 0.f;

    unsigned* bufs[2] = { sW0, sW1 };

    // prefetch W chunk 0 (rides in one group with any pending sA cp.asyncs)
    for (int i = tid; i < KC * 64; i += 256) {
        int k = i >> 6, c4 = (i & 63) * 4;
        cp16(bufs[0] + k * WSTRIDE + c4, Wtf + (size_t)k * DIM + c4);
    }
    CP_COMMIT();

    for (int c = 0; c < NC; c++) {
        unsigned* cur = bufs[c & 1];
        if (c + 1 < NC) {
            const unsigned* src = Wtf + (size_t)(c + 1) * KC * DIM;
            unsigned* nb = bufs[(c + 1) & 1];
            for (int i = tid; i < KC * 64; i += 256) {
                int k = i >> 6, c4 = (i & 63) * 4;
                cp16(nb + k * WSTRIDE + c4, src + (size_t)k * DIM + c4);
            }
            CP_COMMIT();
            asm volatile("cp.async.wait_group 1;\n");
        } else {
            asm volatile("cp.async.wait_group 0;\n");
        }
        __syncthreads();   // cur buffer (and, at c==0, sA) visible to all

        int kc = c * KC;
#pragma unroll
        for (int ks = 0; ks < KC; ks += 8) {
            unsigned a[2][4];
#pragma unroll
            for (int mf = 0; mf < 2; mf++) {
                const float* p = sA + (warp_m * 32 + mf * 16 + g) * ASTRIDE + kc + ks + t;
                a[mf][0] = f2tf(p[0]);
                a[mf][1] = f2tf(p[8 * ASTRIDE]);
                a[mf][2] = f2tf(p[4]);
                a[mf][3] = f2tf(p[8 * ASTRIDE + 4]);
            }
            unsigned b[8][2];
#pragma unroll
            for (int nf = 0; nf < 8; nf++) {
                const unsigned* p = cur + (ks + t) * WSTRIDE + warp_n * 64 + nf * 8 + g;
                b[nf][0] = p[0];
                b[nf][1] = p[4 * WSTRIDE];
            }
#pragma unroll
            for (int mf = 0; mf < 2; mf++)
#pragma unroll
                for (int nf = 0; nf < 8; nf++)
                    mma_tf32(acc[mf][nf], a[mf], b[nf]);
        }
        __syncthreads();   // reads of cur done before it is refilled next iter
    }
}

// ---- weight preconvert: g_Wtf <- tf32(Wu | Wg1 | Wg2) ----
__global__ void kW(const float* __restrict__ Wu, const float* __restrict__ Wg) {
    int i = blockIdx.x * blockDim.x + threadIdx.x;
    if (i < DIM * DIM)            g_Wtf[i] = f2tf(Wu[i]);
    else if (i < 3 * DIM * DIM)   g_Wtf[i] = f2tf(Wg[i - DIM * DIM]);
}

// ---- flag pipeline for masked base copy ----
__global__ void kZero(int n4) {
    int i = blockIdx.x * blockDim.x + threadIdx.x;
    if (i < n4) ((int*)g_flag)[i] = 0;
}
__global__ void kSet(const int* __restrict__ keys, int M) {
    int i = blockIdx.x * blockDim.x + threadIdx.x;
    if (i < M) g_flag[keys[i]] = 1;
}
// copy unmapped rows prev -> out (one warp per row)
__global__ void kCopy(const float* __restrict__ prev, float* __restrict__ out, int nrows) {
    int warp = (blockIdx.x * blockDim.x + threadIdx.x) >> 5;
    int lane = threadIdx.x & 31;
    if (warp >= nrows || g_flag[warp]) return;
    const float4* s = (const float4*)(prev + (size_t)warp * DIM);
    float4*       d = (float4*)(out  + (size_t)warp * DIM);
    d[lane]      = s[lane];
    d[lane + 32] = s[lane + 32];
}

// ---- kernel A: U = tanh(cfg@Wu + bu); G2 = U@Wg2 + bg ----
__global__ void __launch_bounds__(256, 2)
kA(const float* __restrict__ cfg, const float* __restrict__ bu,
   const float* __restrict__ bg, int n_cfg)
{
    extern __shared__ char smem[];
    float*    sA  = (float*)smem;
    unsigned* sW0 = (unsigned*)(smem + SMEM_A_BYTES);
    unsigned* sW1 = sW0 + KC * WSTRIDE;
    float*    sBu = (float*)(smem + SMEM_A_BYTES + 2 * SMEM_W_BYTES);
    float*    sBg = sBu + DIM;   // sBu+sBg fill the 2KB misc region exactly

    int tid = threadIdx.x;
    int warp = tid >> 5, lane = tid & 31;
    int warp_m = warp >> 2, warp_n = warp & 3;
    int g = lane >> 2, t = lane & 3;
    int r0 = blockIdx.x * BM;

    if (tid < DIM) { sBu[tid] = bu[tid]; sBg[tid] = bg[tid]; }

    // gather cfg tile via cp.async (zero-fill tail rows); committed inside gemm_tile
    for (int i = tid; i < BM * 64; i += 256) {
        int row = i >> 6, c4 = (i & 63) * 4;
        int ok = (r0 + row < n_cfg) ? 16 : 0;
        cp16z(sA + row * ASTRIDE + c4, cfg + (size_t)(r0 + row) * DIM + c4, ok);
    }

    float acc[2][8][4];
    gemm_tile(sA, sW0, sW1, g_Wtf, acc, tid, warp_m, warp_n, g, t);   // cfg @ Wu
    __syncthreads();   // all GEMM1 reads of sA done before u overwrites it

    // epilogue 1: u = tanh(. + bu) -> sA (input of GEMM2) and g_U
#pragma unroll
    for (int mf = 0; mf < 2; mf++)
#pragma unroll
        for (int nf = 0; nf < 8; nf++)
#pragma unroll
            for (int i = 0; i < 4; i++) {
                int row_l = warp_m * 32 + mf * 16 + g + ((i >= 2) ? 8 : 0);
                int col   = warp_n * 64 + nf * 8 + 2 * t + (i & 1);
                float u = tanhf(acc[mf][nf][i] + sBu[col]);
                sA[row_l * ASTRIDE + col] = u;
                if (r0 + row_l < n_cfg)
                    g_U[(size_t)(r0 + row_l) * DIM + col] = u;
            }
    // gemm_tile's first in-loop __syncthreads orders these sA writes

    gemm_tile(sA, sW0, sW1, g_Wtf + 2 * DIM * DIM, acc, tid, warp_m, warp_n, g, t);  // u @ Wg2

#pragma unroll
    for (int mf = 0; mf < 2; mf++)
#pragma unroll
        for (int nf = 0; nf < 8; nf++)
#pragma unroll
            for (int i = 0; i < 4; i++) {
                int row_l = warp_m * 32 + mf * 16 + g + ((i >= 2) ? 8 : 0);
                int col   = warp_n * 64 + nf * 8 + 2 * t + (i & 1);
                if (r0 + row_l < n_cfg)
                    g_G2[(size_t)(r0 + row_l) * DIM + col] = acc[mf][nf][i] + sBg[col];
            }
}

// ---- kernel B: z = sigmoid(prev[key]@Wg1 + G2[val]); out[key] = z*prev + (1-z)*U[val] ----
__global__ void __launch_bounds__(256, 2)
kB(const float* __restrict__ prev, const int* __restrict__ keys,
   const int* __restrict__ vals, float* __restrict__ out, int M)
{
    extern __shared__ char smem[];
    float*    sA   = (float*)smem;
    unsigned* sW0  = (unsigned*)(smem + SMEM_A_BYTES);
    unsigned* sW1  = sW0 + KC * WSTRIDE;
    int*      sKey = (int*)(smem + SMEM_A_BYTES + 2 * SMEM_W_BYTES);
    int*      sVal = sKey + BM;

    int tid = threadIdx.x;
    int warp = tid >> 5, lane = tid & 31;
    int warp_m = warp >> 2, warp_n = warp & 3;
    int g = lane >> 2, t = lane & 3;
    int r0 = blockIdx.x * BM;

    if (tid < BM) {
        int idx = r0 + tid;
        sKey[tid] = (idx < M) ? keys[idx] : 0;
        sVal[tid] = (idx < M) ? vals[idx] : 0;
    }
    __syncthreads();

    // gather prev rows via cp.async; committed with W chunk 0 inside gemm_tile
    for (int i = tid; i < BM * 64; i += 256) {
        int row = i >> 6, c4 = (i & 63) * 4;
        cp16(sA + row * ASTRIDE + c4, prev + (size_t)sKey[row] * DIM + c4);
    }

    float acc[2][8][4];
    gemm_tile(sA, sW0, sW1, g_Wtf + DIM * DIM, acc, tid, warp_m, warp_n, g, t);  // prev_g @ Wg1

#pragma unroll
    for (int mf = 0; mf < 2; mf++)
#pragma unroll
        for (int nf = 0; nf < 8; nf++)
#pragma unroll
            for (int i = 0; i < 4; i++) {
                int row_l = warp_m * 32 + mf * 16 + g + ((i >= 2) ? 8 : 0);
                int col   = warp_n * 64 + nf * 8 + 2 * t + (i & 1);
                if (r0 + row_l < M) {
                    int key = sKey[row_l];
                    int val = sVal[row_l];
                    float pv = sA[row_l * ASTRIDE + col];
                    float s  = acc[mf][nf][i] + g_G2[(size_t)val * DIM + col];
                    float z  = 1.f / (1.f + __expf(-s));
                    float uv = g_U[(size_t)val * DIM + col];
                    out[(size_t)key * DIM + col] = z * pv + (1.f - z) * uv;
                }
            }
}

extern "C" void kernel_launch(void* const* d_in, const int* in_sizes, int n_in,
                              void* d_out, int out_size)
{
    if (n_in < 8) return;
    const float* prev = (const float*)d_in[0];
    const float* cfg  = (const float*)d_in[1];
    const int*   mk   = (const int*)d_in[2];
    const int*   mv   = (const int*)d_in[3];
    const float* Wu   = (const float*)d_in[4];
    const float* bu   = (const float*)d_in[5];
    const float* Wg   = (const float*)d_in[6];
    const float* bg   = (const float*)d_in[7];
    float* out = (float*)d_out;

    int n_ast = in_sizes[0] / DIM;
    int n_cfg = in_sizes[1] / DIM;
    int M     = in_sizes[2];

    cudaFuncSetAttribute(kA, cudaFuncAttributeMaxDynamicSharedMemorySize, SMEM_TOTAL);
    cudaFuncSetAttribute(kB, cudaFuncAttributeMaxDynamicSharedMemorySize, SMEM_TOTAL);

    // weights -> tf32 once per launch
    kW<<<(3 * DIM * DIM + 255) / 256, 256>>>(Wu, Wg);

    // masked base copy: only unmapped rows
    int n4 = (n_ast + 3) / 4;
    kZero<<<(n4 + 255) / 256, 256>>>(n4);
    kSet<<<(M + 255) / 256, 256>>>(mk, M);
    kCopy<<<(n_ast * 32 + 255) / 256, 256>>>(prev, out, n_ast);

    kA<<<(n_cfg + BM - 1) / BM, 256, SMEM_TOTAL>>>(cfg, bu, bg, n_cfg);
    kB<<<(M + BM - 1) / BM, 256, SMEM_TOTAL>>>(prev, mk, mv, out, M);
}

// round 14
// speedup vs baseline: 1.5851x; 1.0262x over previous
#include <cuda_runtime.h>
#include <cuda_fp16.h>
#include <math.h>
#include <stdint.h>

#define DIM 256
#define BM 64
#define KC 32
#define NC (DIM / KC)      // 8 chunks
#define ASTH 264           // sA row stride (halves): bank = 4g+t -> conflict-free
#define WSTH 40            // sW row stride (halves): bank = 20g+t -> conflict-free
#define MAX_CFG 100000
#define NR_AST  500000

// ---- allocation-free scratch ----
__device__ float  g_U [(size_t)MAX_CFG * DIM];
__device__ float  g_G2[(size_t)MAX_CFG * DIM];
__device__ __half g_Wh[3 * DIM * DIM];     // transposed fp16: [mat][n*256 + k]
__device__ unsigned char g_flag[NR_AST];

#define SMEM_A_BYTES (BM * ASTH * 2)           // 33792
#define SMEM_W_BYTES (DIM * WSTH * 2)          // 20480 per buffer
#define SMEM_TOTAL   (SMEM_A_BYTES + 2 * SMEM_W_BYTES + 2048)   // 76800 -> 2 CTAs/SM

__device__ __forceinline__ uint32_t smem_u32(const void* p) {
    uint32_t a;
    asm("{ .reg .u64 t; cvta.to.shared.u64 t, %1; cvt.u32.u64 %0, t; }" : "=r"(a) : "l"(p));
    return a;
}
__device__ __forceinline__ void cp16(void* s, const void* g) {
    uint32_t sa = smem_u32(s);
    asm volatile("cp.async.cg.shared.global [%0], [%1], 16;\n" :: "r"(sa), "l"(g));
}
#define CP_COMMIT() asm volatile("cp.async.commit_group;\n" ::: "memory")

__device__ __forceinline__ float sigmoidf_(float x) { return 1.f / (1.f + __expf(-x)); }

// fp16 MMA, fp32 accum: D(16x8) += A(16x16,row) * B(16x8,col)
__device__ __forceinline__ void mma_f16(float c[4], const unsigned a[4], const unsigned b[2]) {
    asm volatile(
        "mma.sync.aligned.m16n8k16.row.col.f32.f16.f16.f32 "
        "{%0,%1,%2,%3}, {%4,%5,%6,%7}, {%8,%9}, {%0,%1,%2,%3};"
        : "+f"(c[0]), "+f"(c[1]), "+f"(c[2]), "+f"(c[3])
        : "r"(a[0]), "r"(a[1]), "r"(a[2]), "r"(a[3]), "r"(b[0]), "r"(b[1]));
}

// 64x256x256 tile: sA(half) @ Wh^T (fp16, streamed via double-buffered cp.async).
// 8 warps: warp_m in [0,2) x warp_n in [0,4), 32x64 per warp.
__device__ __forceinline__ void gemm_h(
    const __half* __restrict__ sA, __half* __restrict__ sW0, __half* __restrict__ sW1,
    const __half* __restrict__ Wh, float acc[2][8][4],
    int tid, int warp_m, int warp_n, int g, int t)
{
#pragma unroll
    for (int mf = 0; mf < 2; mf++)
#pragma unroll
        for (int nf = 0; nf < 8; nf++)
#pragma unroll
            for (int i = 0; i < 4; i++) acc[mf][nf][i] = 0.f;

    __half* bufs[2] = { sW0, sW1 };

    // prefetch W chunk 0: 256 n-rows x 32 halves (64B = 4 x cp16 per row)
    for (int i = tid; i < DIM * 4; i += 256) {
        int n = i >> 2, j = i & 3;
        cp16(bufs[0] + n * WSTH + j * 8, Wh + (size_t)n * DIM + j * 8);
    }
    CP_COMMIT();

    for (int c = 0; c < NC; c++) {
        __half* cur = bufs[c & 1];
        if (c + 1 < NC) {
            const __half* src = Wh + (size_t)(c + 1) * KC;   // column offset within rows
            __half* nb = bufs[(c + 1) & 1];
            for (int i = tid; i < DIM * 4; i += 256) {
                int n = i >> 2, j = i & 3;
                cp16(nb + n * WSTH + j * 8, src + (size_t)n * DIM + j * 8);
            }
            CP_COMMIT();
            asm volatile("cp.async.wait_group 1;\n" ::: "memory");
        } else {
            asm volatile("cp.async.wait_group 0;\n" ::: "memory");
        }
        __syncthreads();   // chunk c (and, at c==0, sA stores) visible

        int kc = c * KC;
#pragma unroll
        for (int ks = 0; ks < KC; ks += 16) {
            unsigned a[2][4];
#pragma unroll
            for (int mf = 0; mf < 2; mf++) {
                const __half* p = sA + (warp_m * 32 + mf * 16 + g) * ASTH + kc + ks + 2 * t;
                a[mf][0] = *(const unsigned*)(p);
                a[mf][1] = *(const unsigned*)(p + 8 * ASTH);
                a[mf][2] = *(const unsigned*)(p + 8);
                a[mf][3] = *(const unsigned*)(p + 8 * ASTH + 8);
            }
            unsigned b[8][2];
#pragma unroll
            for (int nf = 0; nf < 8; nf++) {
                const __half* q = cur + (warp_n * 64 + nf * 8 + g) * WSTH + ks + 2 * t;
                b[nf][0] = *(const unsigned*)(q);
                b[nf][1] = *(const unsigned*)(q + 8);
            }
#pragma unroll
            for (int mf = 0; mf < 2; mf++)
#pragma unroll
                for (int nf = 0; nf < 8; nf++)
                    mma_f16(acc[mf][nf], a[mf], b[nf]);
        }
        __syncthreads();   // reads of cur done before refill
    }
}

// ---- weight transpose+convert: g_Wh[mat][n*256+k] = half(W[k][n]) ----
__global__ void kW(const float* __restrict__ Wu, const float* __restrict__ Wg) {
    int i = blockIdx.x * blockDim.x + threadIdx.x;
    if (i >= DIM * DIM) return;
    int n = i & 255, k = i >> 8;
    g_Wh[n * DIM + k]                 = __float2half(Wu[k * DIM + n]);
    g_Wh[DIM * DIM + n * DIM + k]     = __float2half(Wg[k * DIM + n]);
    g_Wh[2 * DIM * DIM + n * DIM + k] = __float2half(Wg[(DIM + k) * DIM + n]);
}

// ---- flag pipeline for masked base copy ----
__global__ void kZero(int n4) {
    int i = blockIdx.x * blockDim.x + threadIdx.x;
    if (i < n4) ((int*)g_flag)[i] = 0;
}
__global__ void kSet(const int* __restrict__ keys, int M) {
    int i = blockIdx.x * blockDim.x + threadIdx.x;
    if (i < M) g_flag[keys[i]] = 1;
}
__global__ void kCopy(const float* __restrict__ prev, float* __restrict__ out, int nrows) {
    int warp = (blockIdx.x * blockDim.x + threadIdx.x) >> 5;
    int lane = threadIdx.x & 31;
    if (warp >= nrows || g_flag[warp]) return;
    const float4* s = (const float4*)(prev + (size_t)warp * DIM);
    float4*       d = (float4*)(out  + (size_t)warp * DIM);
    d[lane]      = s[lane];
    d[lane + 32] = s[lane + 32];
}

// ---- kernel A: U = tanh(cfg@Wu + bu); G2 = U@Wg2 + bg ----
__global__ void __launch_bounds__(256, 2)
kA(const float* __restrict__ cfg, const float* __restrict__ bu,
   const float* __restrict__ bg, int n_cfg)
{
    extern __shared__ char smem[];
    __half* sA  = (__half*)smem;
    __half* sW0 = (__half*)(smem + SMEM_A_BYTES);
    __half* sW1 = sW0 + DIM * WSTH;
    float*  sBu = (float*)(smem + SMEM_A_BYTES + 2 * SMEM_W_BYTES);
    float*  sBg = sBu + DIM;

    int tid = threadIdx.x;
    int warp = tid >> 5, lane = tid & 31;
    int warp_m = warp >> 2, warp_n = warp & 3;
    int g = lane >> 2, t = lane & 3;
    int r0 = blockIdx.x * BM;

    if (tid < DIM) { sBu[tid] = bu[tid]; sBg[tid] = bg[tid]; }

    // gather cfg tile -> half smem (zero-pad tail rows)
    for (int i = tid; i < BM * 64; i += 256) {
        int row = i >> 6, c4 = (i & 63) * 4;
        float4 v = make_float4(0.f, 0.f, 0.f, 0.f);
        if (r0 + row < n_cfg)
            v = *(const float4*)(cfg + (size_t)(r0 + row) * DIM + c4);
        __half2* dst = (__half2*)(sA + row * ASTH + c4);
        dst[0] = __floats2half2_rn(v.x, v.y);
        dst[1] = __floats2half2_rn(v.z, v.w);
    }
    // gemm_h's first in-loop __syncthreads orders these stores

    float acc[2][8][4];
    gemm_h(sA, sW0, sW1, g_Wh, acc, tid, warp_m, warp_n, g, t);   // cfg @ Wu^T
    __syncthreads();   // all GEMM1 reads of sA done before u overwrites it

    // epilogue 1: u = tanh(. + bu) -> sA (half, input of GEMM2) and g_U (f32)
#pragma unroll
    for (int mf = 0; mf < 2; mf++)
#pragma unroll
        for (int nf = 0; nf < 8; nf++)
#pragma unroll
            for (int i = 0; i < 4; i++) {
                int row_l = warp_m * 32 + mf * 16 + g + ((i >= 2) ? 8 : 0);
                int col   = warp_n * 64 + nf * 8 + 2 * t + (i & 1);
                float u = tanhf(acc[mf][nf][i] + sBu[col]);
                sA[row_l * ASTH + col] = __float2half(u);
                if (r0 + row_l < n_cfg)
                    g_U[(size_t)(r0 + row_l) * DIM + col] = u;
            }

    gemm_h(sA, sW0, sW1, g_Wh + 2 * DIM * DIM, acc, tid, warp_m, warp_n, g, t);  // u @ Wg2^T

#pragma unroll
    for (int mf = 0; mf < 2; mf++)
#pragma unroll
        for (int nf = 0; nf < 8; nf++)
#pragma unroll
            for (int i = 0; i < 4; i++) {
                int row_l = warp_m * 32 + mf * 16 + g + ((i >= 2) ? 8 : 0);
                int col   = warp_n * 64 + nf * 8 + 2 * t + (i & 1);
                if (r0 + row_l < n_cfg)
                    g_G2[(size_t)(r0 + row_l) * DIM + col] = acc[mf][nf][i] + sBg[col];
            }
}

// ---- kernel B: z = sigmoid(prev[key]@Wg1 + G2[val]); out[key] = z*prev + (1-z)*U[val] ----
__global__ void __launch_bounds__(256, 2)
kB(const float* __restrict__ prev, const int* __restrict__ keys,
   const int* __restrict__ vals, float* __restrict__ out, int M)
{
    extern __shared__ char smem[];
    __half* sA   = (__half*)smem;
    __half* sW0  = (__half*)(smem + SMEM_A_BYTES);
    __half* sW1  = sW0 + DIM * WSTH;
    int*    sKey = (int*)(smem + SMEM_A_BYTES + 2 * SMEM_W_BYTES);
    int*    sVal = sKey + BM;

    int tid = threadIdx.x;
    int warp = tid >> 5, lane = tid & 31;
    int warp_m = warp >> 2, warp_n = warp & 3;
    int g = lane >> 2, t = lane & 3;
    int r0 = blockIdx.x * BM;

    if (tid < BM) {
        int idx = r0 + tid;
        sKey[tid] = (idx < M) ? keys[idx] : 0;
        sVal[tid] = (idx < M) ? vals[idx] : 0;
    }
    __syncthreads();

    // gather prev rows -> half smem
    for (int i = tid; i < BM * 64; i += 256) {
        int row = i >> 6, c4 = (i & 63) * 4;
        float4 v = *(const float4*)(prev + (size_t)sKey[row] * DIM + c4);
        __half2* dst = (__half2*)(sA + row * ASTH + c4);
        dst[0] = __floats2half2_rn(v.x, v.y);
        dst[1] = __floats2half2_rn(v.z, v.w);
    }
    // gemm_h's first in-loop __syncthreads orders these stores

    float acc[2][8][4];
    gemm_h(sA, sW0, sW1, g_Wh + DIM * DIM, acc, tid, warp_m, warp_n, g, t);  // prev_g @ Wg1^T

    // epilogue: gate + mix + scatter (prev re-read in f32 for full precision)
#pragma unroll
    for (int mf = 0; mf < 2; mf++)
#pragma unroll
        for (int nf = 0; nf < 8; nf++)
#pragma unroll
            for (int i = 0; i < 4; i++) {
                int row_l = warp_m * 32 + mf * 16 + g + ((i >= 2) ? 8 : 0);
                int col   = warp_n * 64 + nf * 8 + 2 * t + (i & 1);
                if (r0 + row_l < M) {
                    int key = sKey[row_l];
                    int val = sVal[row_l];
                    float pv = prev[(size_t)key * DIM + col];
                    float s  = acc[mf][nf][i] + g_G2[(size_t)val * DIM + col];
                    float z  = sigmoidf_(s);
                    float uv = g_U[(size_t)val * DIM + col];
                    out[(size_t)key * DIM + col] = z * pv + (1.f - z) * uv;
                }
            }
}

extern "C" void kernel_launch(void* const* d_in, const int* in_sizes, int n_in,
                              void* d_out, int out_size)
{
    if (n_in < 8) return;
    const float* prev = (const float*)d_in[0];
    const float* cfg  = (const float*)d_in[1];
    const int*   mk   = (const int*)d_in[2];
    const int*   mv   = (const int*)d_in[3];
    const float* Wu   = (const float*)d_in[4];
    const float* bu   = (const float*)d_in[5];
    const float* Wg   = (const float*)d_in[6];
    const float* bg   = (const float*)d_in[7];
    float* out = (float*)d_out;

    int n_ast = in_sizes[0] / DIM;
    int n_cfg = in_sizes[1] / DIM;
    int M     = in_sizes[2];

    cudaFuncSetAttribute(kA, cudaFuncAttributeMaxDynamicSharedMemorySize, SMEM_TOTAL);
    cudaFuncSetAttribute(kB, cudaFuncAttributeMaxDynamicSharedMemorySize, SMEM_TOTAL);

    kW<<<(DIM * DIM + 255) / 256, 256>>>(Wu, Wg);

    int n4 = (n_ast + 3) / 4;
    kZero<<<(n4 + 255) / 256, 256>>>(n4);
    kSet<<<(M + 255) / 256, 256>>>(mk, M);
    kCopy<<<(n_ast * 32 + 255) / 256, 256>>>(prev, out, n_ast);

    kA<<<(n_cfg + BM - 1) / BM, 256, SMEM_TOTAL>>>(cfg, bu, bg, n_cfg);
    kB<<<(M + BM - 1) / BM, 256, SMEM_TOTAL>>>(prev, mk, mv, out, M);
}